// round 1
// baseline (speedup 1.0000x reference)
#include <cuda_runtime.h>
#include <cstdint>

// ---------------------------------------------------------------------------
// Dcls1d: x(8,256,2048) f32, weight(256,256,16), P(1,256,256,16), bias(256)
// Step 1: construct dense kernel K(256 o, 256 i, 33 d) from weight+P.
//         frac comes from out-channel 0 (faithful to reference).
// Step 2: conv1d, pad=16, stride=1 -> out(8,256,2048).
// ---------------------------------------------------------------------------

#define B_   8
#define C_   256
#define T_   2048
#define O_   256
#define DKS_ 33
#define PAD_ 16
#define KC_  16

// Scratch: constructed kernel, 256*256*33 floats = 8.65 MB (static device global)
__device__ float g_K[O_ * C_ * DKS_];

// ---------------------------------------------------------------------------
// Kernel 1: build the interpolated kernel.
// One thread per (o, i): 16 taps scattered into a 33-entry accumulator.
// ---------------------------------------------------------------------------
__global__ void build_kernel(const float* __restrict__ w,
                             const float* __restrict__ P) {
    int oi = blockIdx.x * blockDim.x + threadIdx.x;
    if (oi >= O_ * C_) return;
    int ig = oi & (C_ - 1);            // input channel

    float acc[DKS_];
#pragma unroll
    for (int d = 0; d < DKS_; ++d) acc[d] = 0.f;

    const float* Prow  = P + (size_t)oi * KC_;          // P[0, o, ig, :]
    const float* P0row = P + (size_t)ig * KC_;          // P[0, 0, ig, :]  (frac source!)
    const float* Wrow  = w + (size_t)oi * KC_;

#pragma unroll
    for (int k = 0; k < KC_; ++k) {
        float pp  = Prow[k] + (float)(DKS_ / 2);        // in [0, 32]
        int   p   = (int)floorf(pp);
        float pp0 = P0row[k] + (float)(DKS_ / 2);
        float fr  = pp0 - floorf(pp0);                  // frac from o=0 row
        float wv  = Wrow[k];
        if (p >= 0 && p < DKS_)       acc[p]     += wv * (1.f - fr);
        if (p + 1 >= 0 && p + 1 < DKS_) acc[p + 1] += wv * fr;
    }

    float* out = g_K + (size_t)oi * DKS_;
#pragma unroll
    for (int d = 0; d < DKS_; ++d) out[d] = acc[d];
}

// ---------------------------------------------------------------------------
// Kernel 2: the convolution.
// Block tile: 64 out-channels x 64 time steps, one batch. 256 threads.
// Thread tile: 4 o x 4 t. Loop over 256 input channels; per channel:
//   - stage x row (97 floats, halo 16 each side) in smem
//   - stage K tile (64 x 33) in smem
//   - inner d-loop with sliding x register window (1 LDS/d for x).
// ---------------------------------------------------------------------------
#define O_TILE 64
#define T_TILE 64

__global__ __launch_bounds__(256, 4)
void conv_kernel(const float* __restrict__ x,
                 const float* __restrict__ bias,
                 float* __restrict__ out) {
    __shared__ float xs[T_TILE + DKS_ + 1];       // 98 floats (last slot = shift slack)
    __shared__ float ks[O_TILE * DKS_];           // 64*33 = 2112 floats

    const int b  = blockIdx.z;
    const int o0 = blockIdx.y * O_TILE;
    const int t0 = blockIdx.x * T_TILE;
    const int tid = threadIdx.x;
    const int tx = tid & 15;                      // 16 t-groups
    const int ty = tid >> 4;                      // 16 o-groups
    const int tt = tx * 4;

    float acc[4][4];
#pragma unroll
    for (int a = 0; a < 4; ++a)
#pragma unroll
        for (int j = 0; j < 4; ++j) acc[a][j] = 0.f;

    const float* xb = x + (size_t)b * C_ * T_;

    for (int i = 0; i < C_; ++i) {
        // --- stage x row: xs[j] = x[b, i, t0 + j - 16] (zero-padded) ---
        if (tid < T_TILE + 2 * PAD_ + 2) {        // 98 entries (slot 97 is slack)
            int t = t0 + tid - PAD_;
            xs[tid] = (t >= 0 && t < T_ && tid < T_TILE + 2 * PAD_)
                          ? xb[(size_t)i * T_ + t] : 0.f;
        }
        // --- stage K tile ---
        const float* kg = g_K + ((size_t)o0 * C_ + i) * DKS_;
        for (int idx = tid; idx < O_TILE * DKS_; idx += 256) {
            int oo = idx / DKS_;
            int d  = idx - oo * DKS_;
            ks[idx] = kg[(size_t)oo * C_ * DKS_ + d];
        }
        __syncthreads();

        // --- compute: sliding window over d ---
        float w0 = xs[tt + 0], w1 = xs[tt + 1], w2 = xs[tt + 2], w3 = xs[tt + 3];
#pragma unroll
        for (int d = 0; d < DKS_; ++d) {
            float kv0 = ks[(ty * 4 + 0) * DKS_ + d];
            float kv1 = ks[(ty * 4 + 1) * DKS_ + d];
            float kv2 = ks[(ty * 4 + 2) * DKS_ + d];
            float kv3 = ks[(ty * 4 + 3) * DKS_ + d];

            acc[0][0] += kv0 * w0; acc[0][1] += kv0 * w1; acc[0][2] += kv0 * w2; acc[0][3] += kv0 * w3;
            acc[1][0] += kv1 * w0; acc[1][1] += kv1 * w1; acc[1][2] += kv1 * w2; acc[1][3] += kv1 * w3;
            acc[2][0] += kv2 * w0; acc[2][1] += kv2 * w1; acc[2][2] += kv2 * w2; acc[2][3] += kv2 * w3;
            acc[3][0] += kv3 * w0; acc[3][1] += kv3 * w1; acc[3][2] += kv3 * w2; acc[3][3] += kv3 * w3;

            // shift window (last iteration reads slack slot 97; value unused)
            w0 = w1; w1 = w2; w2 = w3; w3 = xs[tt + 4 + d];
        }
        __syncthreads();
    }

    // --- epilogue: add bias, store ---
#pragma unroll
    for (int a = 0; a < 4; ++a) {
        int o = o0 + ty * 4 + a;
        float bv = bias[o];
        float* orow = out + ((size_t)b * O_ + o) * T_ + t0 + tt;
#pragma unroll
        for (int j = 0; j < 4; ++j) orow[j] = acc[a][j] + bv;
    }
}

// ---------------------------------------------------------------------------
// Launch
// ---------------------------------------------------------------------------
extern "C" void kernel_launch(void* const* d_in, const int* in_sizes, int n_in,
                              void* d_out, int out_size) {
    const float* x      = (const float*)d_in[0];
    const float* weight = (const float*)d_in[1];
    const float* P      = (const float*)d_in[2];
    const float* bias   = (const float*)d_in[3];
    float* out          = (float*)d_out;

    build_kernel<<<(O_ * C_ + 255) / 256, 256>>>(weight, P);

    dim3 grid(T_ / T_TILE, O_ / O_TILE, B_);
    conv_kernel<<<grid, 256>>>(x, bias, out);
}

// round 3
// speedup vs baseline: 3.3834x; 3.3834x over previous
#include <cuda_runtime.h>
#include <cuda_bf16.h>
#include <cstdint>

// ---------------------------------------------------------------------------
// Dcls1d via mma.sync (HMMA) bf16 split-GEMM (compute_103-safe PTX).
//   out[b,o,t] = bias[o] + sum_{d,i} K2[d,o,i] * x[b,i,t+d-16]
//   fp32 emulated as bf16 hi+lo, 3 products (hh, hl, lh), fp32 accum.
// ---------------------------------------------------------------------------

#define B_   8
#define C_   256
#define T_   2048
#define O_   256
#define DKS_ 33
#define KC_  16
#define TP_  2080   // 16 + 2048 + 16 padded time rows

__device__ __nv_bfloat16 g_Khi[DKS_ * O_ * C_];   // [d][o][i]
__device__ __nv_bfloat16 g_Klo[DKS_ * O_ * C_];
__device__ __nv_bfloat16 g_Xhi[B_ * TP_ * C_];    // [b][t+16][i]
__device__ __nv_bfloat16 g_Xlo[B_ * TP_ * C_];

// ---- PTX helpers -----------------------------------------------------------
__device__ __forceinline__ uint32_t smem_u32(const void* p) {
    uint32_t a;
    asm("{ .reg .u64 t; cvta.to.shared.u64 t, %1; cvt.u32.u64 %0, t; }"
        : "=r"(a) : "l"(p));
    return a;
}
__device__ __forceinline__ void cpa16(uint32_t dst, const void* src) {
    asm volatile("cp.async.ca.shared.global [%0], [%1], 16;" :: "r"(dst), "l"(src));
}
#define CP_COMMIT() asm volatile("cp.async.commit_group;" ::: "memory")
#define CP_WAIT0()  asm volatile("cp.async.wait_group 0;" ::: "memory")

__device__ __forceinline__ void ldmx4(uint32_t* r, uint32_t addr) {
    asm volatile("ldmatrix.sync.aligned.m8n8.x4.shared.b16 {%0,%1,%2,%3}, [%4];"
                 : "=r"(r[0]), "=r"(r[1]), "=r"(r[2]), "=r"(r[3]) : "r"(addr));
}
#define MMA(dv, a, b0v, b1v)                                                   \
    asm volatile("mma.sync.aligned.m16n8k16.row.col.f32.bf16.bf16.f32 "        \
                 "{%0,%1,%2,%3},{%4,%5,%6,%7},{%8,%9},{%0,%1,%2,%3};"          \
                 : "+f"((dv)[0]), "+f"((dv)[1]), "+f"((dv)[2]), "+f"((dv)[3])  \
                 : "r"((a)[0]), "r"((a)[1]), "r"((a)[2]), "r"((a)[3]),         \
                   "r"(b0v), "r"(b1v))

// ---------------------------------------------------------------------------
// Prep 1: build K2 (bf16 hi/lo), layout [d][o][i].
// ---------------------------------------------------------------------------
__global__ void build_k2(const float* __restrict__ w, const float* __restrict__ P) {
    int oi = blockIdx.x * 256 + threadIdx.x;
    int ig = oi & 255;
    float acc[DKS_];
#pragma unroll
    for (int d = 0; d < DKS_; ++d) acc[d] = 0.f;

    const float* Prow  = P + (size_t)oi * KC_;
    const float* P0row = P + (size_t)ig * KC_;    // out-channel 0 (frac source)
    const float* Wrow  = w + (size_t)oi * KC_;
#pragma unroll
    for (int k = 0; k < KC_; ++k) {
        float pp  = Prow[k] + 16.f;
        int   p   = (int)floorf(pp);
        float pp0 = P0row[k] + 16.f;
        float fr  = pp0 - floorf(pp0);
        float wv  = Wrow[k];
        if (p >= 0 && p < DKS_)         acc[p]     += wv * (1.f - fr);
        if (p + 1 >= 0 && p + 1 < DKS_) acc[p + 1] += wv * fr;
    }
#pragma unroll
    for (int d = 0; d < DKS_; ++d) {
        float v = acc[d];
        __nv_bfloat16 h = __float2bfloat16(v);
        __nv_bfloat16 l = __float2bfloat16(v - __bfloat162float(h));
        size_t idx = (size_t)(d * O_ + (oi >> 8)) * C_ + ig;
        g_Khi[idx] = h;
        g_Klo[idx] = l;
    }
}

// ---------------------------------------------------------------------------
// Prep 2: transpose+split x -> g_Xhi/lo [b][t+16][i]
// ---------------------------------------------------------------------------
__global__ void xsplit(const float* __restrict__ x) {
    __shared__ float sm[32][33];
    int t0 = blockIdx.x * 32, i0 = blockIdx.y * 32, b = blockIdx.z;
    int tl = threadIdx.x & 31, th = threadIdx.x >> 5;
#pragma unroll
    for (int k = 0; k < 4; ++k) {
        int i = i0 + th + k * 8;
        sm[th + k * 8][tl] = x[((size_t)b * C_ + i) * T_ + t0 + tl];
    }
    __syncthreads();
#pragma unroll
    for (int k = 0; k < 4; ++k) {
        int t = t0 + th + k * 8;
        float v = sm[tl][th + k * 8];
        __nv_bfloat16 h = __float2bfloat16(v);
        __nv_bfloat16 l = __float2bfloat16(v - __bfloat162float(h));
        size_t idx = ((size_t)b * TP_ + t + 16) * C_ + i0 + tl;
        g_Xhi[idx] = h;
        g_Xlo[idx] = l;
    }
}

__global__ void zpad() {
    int idx = blockIdx.x * 1024 + threadIdx.x;     // 65536 total
    int b = idx >> 13, r = (idx >> 8) & 31, i = idx & 255;
    int row = (r < 16) ? r : (TP_ - 32 + r);
    size_t o = ((size_t)b * TP_ + row) * C_ + i;
    g_Xhi[o] = __float2bfloat16(0.f);
    g_Xlo[o] = __float2bfloat16(0.f);
}

// ---------------------------------------------------------------------------
// Main GEMM kernel.
// Block: 128 o x 128 t, 256 threads (8 warps: 4 M x 2 N, warp = 32 o x 64 t).
// smem rows have 80B stride -> conflict-free ldmatrix without swizzle.
//   A (K2[d] tile): 128 rows x 32 i, hi+lo, double buffered: 4 x 10240 B
//   X tile:         160 rows x 32 i, hi+lo:                  2 x 12800 B
// ---------------------------------------------------------------------------
#define ROWB   80u
#define A_TS   10240u      // one A tensor (128*80)
#define A_BUF  20480u      // hi+lo
#define X_OFF  40960u
#define X_TS   12800u      // one X tensor (160*80)
#define DSMEM  (40960u + 25600u + 256u)

__global__ __launch_bounds__(256, 1)
void conv_mma(const float* __restrict__ bias, float* __restrict__ out) {
    extern __shared__ char dsm_raw[];
    uint32_t raw  = smem_u32(dsm_raw);
    uint32_t base = (raw + 127u) & ~127u;

    const int tid  = threadIdx.x;
    const int lane = tid & 31, w = tid >> 5;
    const int wm = w & 3, wn = w >> 2;            // 4 M-warps x 2 N-warps
    const int b  = blockIdx.x >> 4;
    const int t0 = (blockIdx.x & 15) * 128;
    const int o0 = blockIdx.y * 128;

    const uint32_t A0 = base;
    const uint32_t X0 = base + X_OFF;

    float acc[2][8][4];
#pragma unroll
    for (int mi = 0; mi < 2; ++mi)
#pragma unroll
        for (int nf = 0; nf < 8; ++nf)
#pragma unroll
            for (int q = 0; q < 4; ++q) acc[mi][nf][q] = 0.f;

    // ldmatrix per-lane row/col offsets
    const uint32_t a_r = (lane & 7) + 8 * ((lane >> 3) & 1);
    const uint32_t a_c = (uint32_t)(lane >> 4) * 16;
    const uint32_t b_r = (lane & 7) + 8 * (lane >> 4);
    const uint32_t b_c = (uint32_t)((lane >> 3) & 1) * 16;

    for (int ic = 0; ic < 8; ++ic) {
        // ---- stage X tile (160 rows x 32 i, hi+lo): 1280 x 16B chunks ----
#pragma unroll
        for (int k = 0; k < 5; ++k) {
            int idx = tid + k * 256;
            int tn  = idx >= 640;
            int r   = (idx - tn * 640) >> 2;
            int c   = idx & 3;
            const __nv_bfloat16* src = (tn ? g_Xlo : g_Xhi)
                + ((size_t)(b * TP_ + t0 + r) * 256 + ic * 32 + c * 8);
            cpa16(X0 + (uint32_t)tn * X_TS + r * ROWB + c * 16, src);
        }
        // ---- stage A(d=0) into buf0: 1024 x 16B chunks ----
#pragma unroll
        for (int k = 0; k < 4; ++k) {
            int idx = tid + k * 256;
            int tn  = idx >> 9;
            int r   = (idx >> 2) & 127;
            int c   = idx & 3;
            const __nv_bfloat16* src = (tn ? g_Klo : g_Khi)
                + ((size_t)(o0 + r) * 256 + ic * 32 + c * 8);
            cpa16(A0 + (uint32_t)tn * A_TS + r * ROWB + c * 16, src);
        }
        CP_COMMIT();
        CP_WAIT0();
        __syncthreads();

        for (int d = 0; d < DKS_; ++d) {
            const uint32_t Ab = A0 + (uint32_t)(d & 1) * A_BUF;
            // prefetch A(d+1) into other buffer
            if (d < DKS_ - 1) {
#pragma unroll
                for (int k = 0; k < 4; ++k) {
                    int idx = tid + k * 256;
                    int tn  = idx >> 9;
                    int r   = (idx >> 2) & 127;
                    int c   = idx & 3;
                    const __nv_bfloat16* src = (tn ? g_Klo : g_Khi)
                        + ((size_t)((d + 1) * 256 + o0 + r) * 256 + ic * 32 + c * 8);
                    cpa16(A0 + (uint32_t)((d + 1) & 1) * A_BUF
                          + (uint32_t)tn * A_TS + r * ROWB + c * 16, src);
                }
                CP_COMMIT();
            }

            // ---- compute d: 2 k-steps x (16 frags x 3 products) ----
#pragma unroll
            for (int kk = 0; kk < 2; ++kk) {
                uint32_t ah[2][4], al[2][4];
#pragma unroll
                for (int mi = 0; mi < 2; ++mi) {
                    uint32_t ad = Ab + (wm * 32 + mi * 16 + a_r) * ROWB
                                + kk * 32 + a_c;
                    ldmx4(ah[mi], ad);
                    ldmx4(al[mi], ad + A_TS);
                }
#pragma unroll
                for (int p = 0; p < 4; ++p) {
                    uint32_t bh[4], bl[4];
                    uint32_t bd = X0 + (wn * 64 + d + p * 16 + b_r) * ROWB
                                + kk * 32 + b_c;
                    ldmx4(bh, bd);
                    ldmx4(bl, bd + X_TS);
                    // hh
#pragma unroll
                    for (int mi = 0; mi < 2; ++mi)
#pragma unroll
                        for (int nn = 0; nn < 2; ++nn)
                            MMA(acc[mi][p * 2 + nn], ah[mi], bh[2 * nn], bh[2 * nn + 1]);
                    // hl
#pragma unroll
                    for (int mi = 0; mi < 2; ++mi)
#pragma unroll
                        for (int nn = 0; nn < 2; ++nn)
                            MMA(acc[mi][p * 2 + nn], ah[mi], bl[2 * nn], bl[2 * nn + 1]);
                    // lh
#pragma unroll
                    for (int mi = 0; mi < 2; ++mi)
#pragma unroll
                        for (int nn = 0; nn < 2; ++nn)
                            MMA(acc[mi][p * 2 + nn], al[mi], bh[2 * nn], bh[2 * nn + 1]);
                }
            }
            CP_WAIT0();
            __syncthreads();
        }
    }

    // ---- epilogue: add bias, store float2 (32B segments per lane quad) ----
    const int g = lane >> 2, tg = lane & 3;
#pragma unroll
    for (int mi = 0; mi < 2; ++mi) {
        int o1 = o0 + wm * 32 + mi * 16 + g;
        float bv1 = bias[o1], bv2 = bias[o1 + 8];
        float* r1 = out + ((size_t)(b * O_ + o1)) * T_ + t0 + wn * 64 + tg * 2;
        float* r2 = r1 + 8 * T_;
#pragma unroll
        for (int nf = 0; nf < 8; ++nf) {
            float2 v1 = make_float2(acc[mi][nf][0] + bv1, acc[mi][nf][1] + bv1);
            float2 v2 = make_float2(acc[mi][nf][2] + bv2, acc[mi][nf][3] + bv2);
            *(float2*)(r1 + nf * 8) = v1;
            *(float2*)(r2 + nf * 8) = v2;
        }
    }
}

// ---------------------------------------------------------------------------
// Launch
// ---------------------------------------------------------------------------
extern "C" void kernel_launch(void* const* d_in, const int* in_sizes, int n_in,
                              void* d_out, int out_size) {
    const float* x      = (const float*)d_in[0];
    const float* weight = (const float*)d_in[1];
    const float* P      = (const float*)d_in[2];
    const float* bias   = (const float*)d_in[3];
    float* out          = (float*)d_out;

    build_k2<<<256, 256>>>(weight, P);
    xsplit<<<dim3(T_ / 32, C_ / 32, B_), 256>>>(x);
    zpad<<<64, 1024>>>();

    cudaFuncSetAttribute(conv_mma, cudaFuncAttributeMaxDynamicSharedMemorySize, DSMEM);
    conv_mma<<<dim3(128, 2), 256, DSMEM>>>(bias, out);
}